// round 4
// baseline (speedup 1.0000x reference)
#include <cuda_runtime.h>
#include <cuda_fp16.h>
#include <math.h>

#define N_NODES 50000
#define N_EDGES 400000
#define N_GRAPHS 512
#define F 32
#define NB 32
#define CUTOFF 5.0f
#define FULL 0xffffffffu

// ---------------- device scratch (no allocations allowed) ----------------
__device__ float g_x0[N_NODES * F];                 // x0, later x0'
__device__ float g_yacc[N_NODES * F];               // segment-sum accumulator
__device__ __half g_p2h[(size_t)N_EDGES * F];       // per-edge Wr_last projection (fp16)
__device__ unsigned char g_flag[N_EDGES];           // 1 = edge inside cutoff

__device__ __forceinline__ float siluf(float x) { return x * (1.f / (1.f + __expf(-x))); }

// ---------------- K0: x0 = embed[z], yacc = x0, zero d_out -------------------
__global__ void k_init(const float* __restrict__ embed, const int* __restrict__ z,
                       float* __restrict__ out) {
    int i = blockIdx.x * blockDim.x + threadIdx.x;
    if (i < N_GRAPHS) out[i] = 0.f;
    if (i < N_NODES * F) {
        int n = i >> 5, f = i & 31;
        float v = embed[z[n] * F + f];
        g_x0[i] = v;
        g_yacc[i] = v;
    }
}

// ---------------- K1: edge pass 1 --------------------------------------------
// warp per edge, lane = feature/basis. Weight columns held in registers.
// Packed src/dst + position loads; next-edge indices prefetched (pipeline).
__global__ void k_edge1(const float* __restrict__ pos,
                        const int* __restrict__ src, const int* __restrict__ dst,
                        const float* __restrict__ Wy0, const float* __restrict__ Wx0,
                        const float* __restrict__ Wr) {
    int lane   = threadIdx.x & 31;
    int warp   = blockIdx.x * (blockDim.x >> 5) + (threadIdx.x >> 5);
    int nwarps = gridDim.x * (blockDim.x >> 5);

    // weight columns (lane f) in registers: killed 64 LDS per edge
    float w01c[NB], wrc[NB];
#pragma unroll
    for (int b = 0; b < NB; b++) {
        w01c[b] = __ldg(&Wy0[b * F + lane]) + __ldg(&Wx0[b * F + lane]); // degree-0 block
        wrc[b]  = __ldg(&Wr[b * F + lane]);
    }
    float lb = lgammaf((float)NB) - lgammaf((float)lane + 1.f) - lgammaf((float)NB - (float)lane);
    float kf = (float)lane;

    int e = warp;
    bool have = (e < N_EDGES);
    int sd = 0;
    if (have && lane < 2) sd = __ldg(lane == 0 ? &src[e] : &dst[e]);

    while (have) {
        int s = __shfl_sync(FULL, sd, 0);
        int d = __shfl_sync(FULL, sd, 1);
        float pv = 0.f;
        if (lane < 6) {
            int base = (lane < 3 ? s : d) * 3 + (lane < 3 ? lane : lane - 3);
            pv = __ldg(&pos[base]);
        }
        // prefetch next edge's indices while this one computes
        int e2 = e + nwarps;
        bool have2 = (e2 < N_EDGES);
        int sd2 = 0;
        if (have2 && lane < 2) sd2 = __ldg(lane == 0 ? &src[e2] : &dst[e2]);

        float dx = __shfl_sync(FULL, pv, 0) - __shfl_sync(FULL, pv, 3);
        float dy = __shfl_sync(FULL, pv, 1) - __shfl_sync(FULL, pv, 4);
        float dz = __shfl_sync(FULL, pv, 2) - __shfl_sync(FULL, pv, 5);
        float r = sqrtf(dx * dx + dy * dy + dz * dz + 1e-12f);
        float t = r * (1.f / CUTOFF);

        if (t >= 1.f) {                        // cutoff -> rbf == 0 exactly
            if (lane == 0) g_flag[e] = 0;
        } else {
            if (lane == 0) g_flag[e] = 1;
            float fc = __expf(1.f - __fdividef(1.f, fmaxf(1.f - t * t, 1e-7f)));
            float u = __fdividef(r, r + 1.f);
            u = fminf(fmaxf(u, 1e-7f), 1.f - 1e-7f);
            float rbf = __expf(lb + kf * __logf(u) + ((float)NB - 1.f - kf) * log1pf(-u)) * fc;

            float p1 = 0.f, p2 = 0.f;
#pragma unroll
            for (int b = 0; b < NB; b++) {
                float rb = __shfl_sync(FULL, rbf, b);
                p1 = fmaf(rb, w01c[b], p1);
                p2 = fmaf(rb, wrc[b], p2);
            }
            g_p2h[(size_t)e * F + lane] = __float2half(p2);
            float msg = p1 * __ldg(&g_x0[s * F + lane]);
            atomicAdd(&g_yacc[d * F + lane], msg);
        }
        e = e2; sd = sd2; have = have2;
    }
}

// ---------------- K2: node update 1 (dense->silu->dense, residual) -----------
__global__ void k_node1(const float* __restrict__ W1, const float* __restrict__ b1,
                        const float* __restrict__ W2, const float* __restrict__ b2,
                        const float* __restrict__ c0) {
    int lane   = threadIdx.x & 31;
    int warp   = blockIdx.x * (blockDim.x >> 5) + (threadIdx.x >> 5);
    int nwarps = gridDim.x * (blockDim.x >> 5);
    float w1c[F], w2c[F];
#pragma unroll
    for (int f = 0; f < F; f++) { w1c[f] = __ldg(&W1[f * F + lane]); w2c[f] = __ldg(&W2[f * F + lane]); }
    float sc  = siluf(__ldg(&c0[0]));
    float bb1 = __ldg(&b1[lane]), bb2 = __ldg(&b2[lane]);

    for (int n = warp; n < N_NODES; n += nwarps) {
        float y = g_yacc[n * F + lane];
        float y1 = bb1;
#pragma unroll
        for (int f = 0; f < F; f++) y1 = fmaf(__shfl_sync(FULL, y, f), w1c[f], y1);
        float g = siluf(y1);
        float y2 = bb2;
#pragma unroll
        for (int f = 0; f < F; f++) y2 = fmaf(__shfl_sync(FULL, g, f), w2c[f], y2);
        float xp = g_x0[n * F + lane] + sc * y2;
        g_x0[n * F + lane]   = xp;     // x0' for pass 2
        g_yacc[n * F + lane] = xp;     // init accumulator for y0
    }
}

// ---------------- K3: edge pass 2 — 4 edges/warp, float4, fp16 p2 ------------
__global__ void k_edge2(const int* __restrict__ src, const int* __restrict__ dst) {
    int lane   = threadIdx.x & 31;
    int g      = lane >> 3;          // edge group 0..3
    int j      = lane & 7;           // feature group (4 floats each)
    int warp   = blockIdx.x * (blockDim.x >> 5) + (threadIdx.x >> 5);
    int nwarps = gridDim.x * (blockDim.x >> 5);

    for (int e0 = warp * 4; e0 < N_EDGES; e0 += nwarps * 4) {
        uchar4 fl = *reinterpret_cast<const uchar4*>(&g_flag[e0]);   // uniform 4B
        if (!(fl.x | fl.y | fl.z | fl.w)) continue;                  // all 4 dead
        int sd = 0;
        if (lane < 8) sd = __ldg(lane < 4 ? &src[e0 + lane] : &dst[e0 + (lane - 4)]);
        int s = __shfl_sync(FULL, sd, g);
        int d = __shfl_sync(FULL, sd, 4 + g);
        unsigned char lg = reinterpret_cast<const unsigned char*>(&fl)[g];
        if (lg) {
            uint2 u = *reinterpret_cast<const uint2*>(&g_p2h[(size_t)(e0 + g) * F + j * 4]);
            __half2 h0 = *reinterpret_cast<__half2*>(&u.x);
            __half2 h1 = *reinterpret_cast<__half2*>(&u.y);
            float2 a = __half22float2(h0), b = __half22float2(h1);
            float4 xv = *reinterpret_cast<const float4*>(&g_x0[(size_t)s * F + j * 4]);
            float4 m = make_float4(a.x * xv.x, a.y * xv.y, b.x * xv.z, b.y * xv.w);
            atomicAdd(reinterpret_cast<float4*>(&g_yacc[(size_t)d * F + j * 4]), m);
        }
    }
}

// ---------------- K4: node update 2 + readout, scatter straight to d_out -----
__global__ void k_node2(const float* __restrict__ W11, const float* __restrict__ b11,
                        const float* __restrict__ W21, const float* __restrict__ b21,
                        const float* __restrict__ c1,
                        const float* __restrict__ Wro1, const float* __restrict__ bro1,
                        const float* __restrict__ Wro2, const float* __restrict__ bro2,
                        const float* __restrict__ abias, const int* __restrict__ z,
                        const int* __restrict__ bseg, float* __restrict__ out) {
    int lane   = threadIdx.x & 31;
    int warp   = blockIdx.x * (blockDim.x >> 5) + (threadIdx.x >> 5);
    int nwarps = gridDim.x * (blockDim.x >> 5);
    float w11c[F], w21c[F], wro1c[F];
#pragma unroll
    for (int f = 0; f < F; f++) {
        w11c[f]  = __ldg(&W11[f * F + lane]);
        w21c[f]  = __ldg(&W21[f * F + lane]);
        wro1c[f] = __ldg(&Wro1[f * F + lane]);
    }
    float sc   = siluf(__ldg(&c1[0]));
    float w2c  = __ldg(&Wro2[lane]);
    float bb11 = __ldg(&b11[lane]), bb21 = __ldg(&b21[lane]), bbr = __ldg(&bro1[lane]);
    float br2  = __ldg(&bro2[0]);

    for (int n = warp; n < N_NODES; n += nwarps) {
        float y0 = g_yacc[n * F + lane];
        float a = bb11;
#pragma unroll
        for (int f = 0; f < F; f++) a = fmaf(__shfl_sync(FULL, y0, f), w11c[f], a);
        a = siluf(a);
        float yb = bb21;
#pragma unroll
        for (int f = 0; f < F; f++) yb = fmaf(__shfl_sync(FULL, a, f), w21c[f], yb);
        float xs0 = g_x0[n * F + lane] + sc * yb;
        float h = bbr;
#pragma unroll
        for (int f = 0; f < F; f++) h = fmaf(__shfl_sync(FULL, xs0, f), wro1c[f], h);
        h = siluf(h);
        float part = h * w2c;
#pragma unroll
        for (int off = 16; off; off >>= 1) part += __shfl_xor_sync(FULL, part, off);
        if (lane == 0) {
            float ea = part + br2 + __ldg(&abias[z[n]]);
            atomicAdd(&out[bseg[n]], ea);
        }
    }
}

// ---------------- launch ------------------------------------------------------
extern "C" void kernel_launch(void* const* d_in, const int* in_sizes, int n_in,
                              void* d_out, int out_size) {
    const float* positions  = (const float*)d_in[0];
    const float* embed      = (const float*)d_in[1];
    const float* Wy0        = (const float*)d_in[2];
    const float* Wx0        = (const float*)d_in[3];
    const float* W1_0       = (const float*)d_in[4];
    const float* b1_0       = (const float*)d_in[5];
    const float* W2_0       = (const float*)d_in[6];
    const float* b2_0       = (const float*)d_in[7];
    const float* c0         = (const float*)d_in[8];
    const float* Wr_last    = (const float*)d_in[9];
    const float* W1_1       = (const float*)d_in[10];
    const float* b1_1       = (const float*)d_in[11];
    const float* W2_1       = (const float*)d_in[12];
    const float* b2_1       = (const float*)d_in[13];
    const float* c1         = (const float*)d_in[14];
    const float* Wro1       = (const float*)d_in[15];
    const float* bro1       = (const float*)d_in[16];
    const float* Wro2       = (const float*)d_in[17];
    const float* bro2       = (const float*)d_in[18];
    const float* abias      = (const float*)d_in[19];
    const int*   z          = (const int*)d_in[20];
    const int*   dst_idx    = (const int*)d_in[21];
    const int*   src_idx    = (const int*)d_in[22];
    const int*   bseg       = (const int*)d_in[23];
    float*       out        = (float*)d_out;

    k_init<<<(N_NODES * F + 255) / 256, 256>>>(embed, z, out);
    k_edge1<<<2048, 256>>>(positions, src_idx, dst_idx, Wy0, Wx0, Wr_last);
    k_node1<<<1024, 256>>>(W1_0, b1_0, W2_0, b2_0, c0);
    k_edge2<<<2048, 256>>>(src_idx, dst_idx);
    k_node2<<<1024, 256>>>(W1_1, b1_1, W2_1, b2_1, c1,
                           Wro1, bro1, Wro2, bro2, abias, z, bseg, out);
}